// round 7
// baseline (speedup 1.0000x reference)
#include <cuda_runtime.h>
#include <cuda_bf16.h>
#include <cstdint>
#include <math.h>

// ---------------------------------------------------------------------------
// GPT2 attention block — tf32 mma.sync with k-paired SMEM fragment layouts.
//   x[4096,1024] @ W_attn[1024,3072] + b_attn -> qkv
//   16-head causal flash attention (D=64)     -> att[4096,1024]
//   att @ W_proj[1024,1024] + b_proj          -> out
// ---------------------------------------------------------------------------

#define TT      4096
#define CC      1024
#define NHEAD   16
#define HDIM    64
#define SCALE   0.125f

__device__ float g_qkv[TT * 3 * CC];
__device__ float g_att[TT * CC];

// ---- tf32 helpers ---------------------------------------------------------
__device__ __forceinline__ unsigned cvt_tf32(float x) {
    unsigned u;
    asm("cvt.rna.tf32.f32 %0, %1;" : "=r"(u) : "f"(x));
    return u;
}
__device__ __forceinline__ void mma_tf32(float* d, const unsigned* a,
                                         unsigned b0, unsigned b1) {
    asm volatile(
        "mma.sync.aligned.m16n8k8.row.col.f32.tf32.tf32.f32 "
        "{%0,%1,%2,%3}, {%4,%5,%6,%7}, {%8,%9}, {%0,%1,%2,%3};"
        : "+f"(d[0]), "+f"(d[1]), "+f"(d[2]), "+f"(d[3])
        : "r"(a[0]), "r"(a[1]), "r"(a[2]), "r"(a[3]), "r"(b0), "r"(b1));
}

// ---------------------------------------------------------------------------
// Tensor-core GEMM + bias: C[M,N] = A[M,K] @ B[K,N] + bias
// Block 128x128, BK=32, 256 threads = 8 warps (2x4), warp tile 64x32.
// SMEM stored as k-paired planes: plane (ks,quad) holds uint2{X[k],X[k+4]}.
// Plane stride 264 floats -> conflict-free LDS.64.
// Register-prefetch of next global tile overlapped with MMA.
// ---------------------------------------------------------------------------
#define GPL 264   // floats per plane (132 uint2 slots)

__global__ __launch_bounds__(256)
void gemm_tc(const float* __restrict__ A, const float* __restrict__ B,
             const float* __restrict__ bias, float* __restrict__ C,
             int M, int N, int K)
{
    __shared__ unsigned As[16 * GPL];   // planes (ks,quad) x [m]
    __shared__ unsigned Bs[16 * GPL];   // planes (ks,quad) x [n]

    const int tid  = threadIdx.x;
    const int lane = tid & 31;
    const int qrl  = lane >> 2;
    const int quad = lane & 3;
    const int w    = tid >> 5;
    const int wm   = w >> 2;          // 0..1
    const int wn   = w & 3;           // 0..3
    const int bm   = blockIdx.y * 128;
    const int bn   = blockIdx.x * 128;

    float d[4][4][4];
    #pragma unroll
    for (int im = 0; im < 4; im++)
        #pragma unroll
        for (int jn = 0; jn < 4; jn++)
            #pragma unroll
            for (int r = 0; r < 4; r++) d[im][jn][r] = 0.0f;

    const int NST = K / 32;
    float4 ra[4], rb[4];

    // ---- prefetch tile 0 ----
    #pragma unroll
    for (int i = 0; i < 4; i++) {
        int f = i * 256 + tid;
        int m = f >> 3, c0 = (f & 7) * 4;            // A: row m, k-cols c0..c0+3
        ra[i] = *(const float4*)&A[(size_t)(bm + m) * K + c0];
        int k = f >> 5, n0 = (f & 31) * 4;           // B: k-row, n-cols n0..n0+3
        rb[i] = *(const float4*)&B[(size_t)k * N + bn + n0];
    }
    // ---- store tile 0 ----
    #pragma unroll
    for (int i = 0; i < 4; i++) {
        int f = i * 256 + tid;
        {   // A
            int m = f >> 3, c0 = (f & 7) * 4;
            int ks = c0 >> 3, half = (c0 >> 2) & 1;
            unsigned* p = &As[(ks * 4) * GPL + m * 2 + half];
            p[0 * GPL] = cvt_tf32(ra[i].x);
            p[1 * GPL] = cvt_tf32(ra[i].y);
            p[2 * GPL] = cvt_tf32(ra[i].z);
            p[3 * GPL] = cvt_tf32(ra[i].w);
        }
        {   // B
            int k = f >> 5, n0 = (f & 31) * 4;
            int ks = k >> 3, r8 = k & 7;
            unsigned* p = &Bs[(ks * 4 + (r8 & 3)) * GPL + n0 * 2 + (r8 >> 2)];
            p[0] = cvt_tf32(rb[i].x);
            p[2] = cvt_tf32(rb[i].y);
            p[4] = cvt_tf32(rb[i].z);
            p[6] = cvt_tf32(rb[i].w);
        }
    }
    __syncthreads();

    for (int s = 0; s < NST; s++) {
        // prefetch next tile into registers (overlaps with MMA below)
        if (s + 1 < NST) {
            const long k0 = (long)(s + 1) * 32;
            #pragma unroll
            for (int i = 0; i < 4; i++) {
                int f = i * 256 + tid;
                int m = f >> 3, c0 = (f & 7) * 4;
                ra[i] = *(const float4*)&A[(size_t)(bm + m) * K + k0 + c0];
                int k = f >> 5, n0 = (f & 31) * 4;
                rb[i] = *(const float4*)&B[(size_t)(k0 + k) * N + bn + n0];
            }
        }

        // ---- MMA over the 4 k-steps of this tile ----
        #pragma unroll
        for (int ks = 0; ks < 4; ks++) {
            const unsigned* Ap = &As[(ks * 4 + quad) * GPL];
            const unsigned* Bp = &Bs[(ks * 4 + quad) * GPL];
            unsigned a[4][4];
            #pragma unroll
            for (int im = 0; im < 4; im++) {
                int r0 = wm * 64 + im * 16 + qrl;
                uint2 u0 = *(const uint2*)&Ap[r0 * 2];
                uint2 u1 = *(const uint2*)&Ap[(r0 + 8) * 2];
                a[im][0] = u0.x; a[im][1] = u1.x; a[im][2] = u0.y; a[im][3] = u1.y;
            }
            #pragma unroll
            for (int jn = 0; jn < 4; jn++) {
                int nc = wn * 32 + jn * 8 + qrl;
                uint2 ub = *(const uint2*)&Bp[nc * 2];
                #pragma unroll
                for (int im = 0; im < 4; im++)
                    mma_tf32(d[im][jn], a[im], ub.x, ub.y);
            }
        }
        __syncthreads();

        // ---- store prefetched tile ----
        if (s + 1 < NST) {
            #pragma unroll
            for (int i = 0; i < 4; i++) {
                int f = i * 256 + tid;
                {
                    int m = f >> 3, c0 = (f & 7) * 4;
                    int ks = c0 >> 3, half = (c0 >> 2) & 1;
                    unsigned* p = &As[(ks * 4) * GPL + m * 2 + half];
                    p[0 * GPL] = cvt_tf32(ra[i].x);
                    p[1 * GPL] = cvt_tf32(ra[i].y);
                    p[2 * GPL] = cvt_tf32(ra[i].z);
                    p[3 * GPL] = cvt_tf32(ra[i].w);
                }
                {
                    int k = f >> 5, n0 = (f & 31) * 4;
                    int ks = k >> 3, r8 = k & 7;
                    unsigned* p = &Bs[(ks * 4 + (r8 & 3)) * GPL + n0 * 2 + (r8 >> 2)];
                    p[0] = cvt_tf32(rb[i].x);
                    p[2] = cvt_tf32(rb[i].y);
                    p[4] = cvt_tf32(rb[i].z);
                    p[6] = cvt_tf32(rb[i].w);
                }
            }
            __syncthreads();
        }
    }

    // ---- epilogue + bias ----
    #pragma unroll
    for (int im = 0; im < 4; im++) {
        int r_lo = bm + wm * 64 + im * 16 + qrl;
        #pragma unroll
        for (int jn = 0; jn < 4; jn++) {
            int col = bn + wn * 32 + jn * 8 + 2 * quad;
            float b0 = bias[col], b1 = bias[col + 1];
            float2 v0 = make_float2(d[im][jn][0] + b0, d[im][jn][1] + b1);
            float2 v1 = make_float2(d[im][jn][2] + b0, d[im][jn][3] + b1);
            *(float2*)&C[(size_t)r_lo * N + col]       = v0;
            *(float2*)&C[(size_t)(r_lo + 8) * N + col] = v1;
        }
    }
}

// ---------------------------------------------------------------------------
// Tensor-core causal flash attention (k-paired K and V layouts).
// Block = 128 q rows x one head, 256 threads = 8 warps; warp w owns q rows
// [16w, 16w+16). K planes: (ks,quad)x[key], stride 264. V planes:
// (kc,quad)x[d], stride 136. b-fragments = single LDS.64.
// ---------------------------------------------------------------------------
#define QS_STR 132
#define KPL    264
#define VPL    136
#define PS_STR 132

__global__ __launch_bounds__(256)
void flash_attn_tc()
{
    extern __shared__ unsigned smem[];
    unsigned* Qs  = smem;                    // [64][132]  Q^T (tf32)
    unsigned* Kp  = Qs + HDIM * QS_STR;      // 32 planes x 264
    unsigned* Vp  = Kp + 32 * KPL;           // 64 planes x 136
    unsigned* Psm = Vp + 64 * VPL;           // [128][132] P (tf32)

    const int h    = blockIdx.y;
    const int qt   = (int)gridDim.x - 1 - (int)blockIdx.x;  // heavy first
    const int q0   = qt * 128;
    const int tid  = threadIdx.x;
    const int lane = tid & 31;
    const int w    = tid >> 5;
    const int qrl  = lane >> 2;
    const int quad = lane & 3;

    // ---- load Q tile, transposed, cvt tf32 ----
    #pragma unroll
    for (int i = 0; i < 8; i++) {
        int idx = tid + i * 256;
        int r   = idx >> 4;
        int c4  = (idx & 15) * 4;
        float4 v = *(const float4*)&g_qkv[(size_t)(q0 + r) * (3 * CC) + h * HDIM + c4];
        Qs[(c4 + 0) * QS_STR + r] = cvt_tf32(v.x);
        Qs[(c4 + 1) * QS_STR + r] = cvt_tf32(v.y);
        Qs[(c4 + 2) * QS_STR + r] = cvt_tf32(v.z);
        Qs[(c4 + 3) * QS_STR + r] = cvt_tf32(v.w);
    }

    float o[8][4];
    #pragma unroll
    for (int n = 0; n < 8; n++)
        #pragma unroll
        for (int r = 0; r < 4; r++) o[n][r] = 0.0f;
    float m_lo = -1e30f, m_hi = -1e30f, l_lo = 0.0f, l_hi = 0.0f;

    for (int kt = 0; kt <= qt; kt++) {
        const int k0 = kt * 128;

        // ---- load K (paired along d) and V (paired along key), cvt tf32 ----
        #pragma unroll
        for (int i = 0; i < 8; i++) {
            int idx = tid + i * 256;
            int r   = idx >> 4;           // key row 0..127
            int c4  = (idx & 15) * 4;     // d
            const float* kro = &g_qkv[(size_t)(k0 + r) * (3 * CC) + CC + h * HDIM + c4];
            float4 kv = *(const float4*)kro;
            {
                int ks = c4 >> 3, half = (c4 >> 2) & 1;
                unsigned* p = &Kp[(ks * 4) * KPL + r * 2 + half];
                p[0 * KPL] = cvt_tf32(kv.x);
                p[1 * KPL] = cvt_tf32(kv.y);
                p[2 * KPL] = cvt_tf32(kv.z);
                p[3 * KPL] = cvt_tf32(kv.w);
            }
            float4 vv = *(const float4*)(kro + CC);
            {
                int kc = r >> 3, r8 = r & 7;
                unsigned* p = &Vp[(kc * 4 + (r8 & 3)) * VPL + c4 * 2 + (r8 >> 2)];
                p[0] = cvt_tf32(vv.x);
                p[2] = cvt_tf32(vv.y);
                p[4] = cvt_tf32(vv.z);
                p[6] = cvt_tf32(vv.w);
            }
        }
        __syncthreads();

        // ---- S = Q K^T (16 rows x 128 cols per warp) ----
        float s[16][4];
        #pragma unroll
        for (int j = 0; j < 16; j++)
            #pragma unroll
            for (int r = 0; r < 4; r++) s[j][r] = 0.0f;

        #pragma unroll
        for (int ks = 0; ks < 8; ks++) {
            const int kk = ks * 8 + quad;
            unsigned a[4];
            a[0] = Qs[kk * QS_STR + w * 16 + qrl];
            a[1] = Qs[kk * QS_STR + w * 16 + qrl + 8];
            a[2] = Qs[(kk + 4) * QS_STR + w * 16 + qrl];
            a[3] = Qs[(kk + 4) * QS_STR + w * 16 + qrl + 8];
            const unsigned* Kpp = &Kp[(ks * 4 + quad) * KPL];
            #pragma unroll
            for (int j = 0; j < 16; j++) {
                uint2 ub = *(const uint2*)&Kpp[(j * 8 + qrl) * 2];
                mma_tf32(s[j], a, ub.x, ub.y);
            }
        }

        // ---- scale + causal mask + row max ----
        float tm_lo = -1e30f, tm_hi = -1e30f;
        #pragma unroll
        for (int j = 0; j < 16; j++) {
            #pragma unroll
            for (int r = 0; r < 4; r++) s[j][r] *= SCALE;
            if (kt == qt) {
                int col = j * 8 + 2 * quad;
                int rl  = w * 16 + qrl;
                int rh  = rl + 8;
                if (col > rl)     s[j][0] = -1e30f;
                if (col + 1 > rl) s[j][1] = -1e30f;
                if (col > rh)     s[j][2] = -1e30f;
                if (col + 1 > rh) s[j][3] = -1e30f;
            }
            tm_lo = fmaxf(tm_lo, fmaxf(s[j][0], s[j][1]));
            tm_hi = fmaxf(tm_hi, fmaxf(s[j][2], s[j][3]));
        }
        tm_lo = fmaxf(tm_lo, __shfl_xor_sync(0xffffffffu, tm_lo, 1));
        tm_lo = fmaxf(tm_lo, __shfl_xor_sync(0xffffffffu, tm_lo, 2));
        tm_hi = fmaxf(tm_hi, __shfl_xor_sync(0xffffffffu, tm_hi, 1));
        tm_hi = fmaxf(tm_hi, __shfl_xor_sync(0xffffffffu, tm_hi, 2));

        float mn_lo = fmaxf(m_lo, tm_lo);
        float mn_hi = fmaxf(m_hi, tm_hi);
        float al_lo = __expf(m_lo - mn_lo);
        float al_hi = __expf(m_hi - mn_hi);
        m_lo = mn_lo; m_hi = mn_hi;
        #pragma unroll
        for (int n = 0; n < 8; n++) {
            o[n][0] *= al_lo; o[n][1] *= al_lo;
            o[n][2] *= al_hi; o[n][3] *= al_hi;
        }

        // ---- exp + row sum + stage P (tf32) ----
        float rs_lo = 0.0f, rs_hi = 0.0f;
        const int rl = w * 16 + qrl;
        #pragma unroll
        for (int j = 0; j < 16; j++) {
            float p0 = __expf(s[j][0] - mn_lo);
            float p1 = __expf(s[j][1] - mn_lo);
            float p2 = __expf(s[j][2] - mn_hi);
            float p3 = __expf(s[j][3] - mn_hi);
            rs_lo += p0 + p1;
            rs_hi += p2 + p3;
            uint2 ulo = make_uint2(cvt_tf32(p0), cvt_tf32(p1));
            uint2 uhi = make_uint2(cvt_tf32(p2), cvt_tf32(p3));
            *(uint2*)&Psm[(size_t)rl * PS_STR + j * 8 + 2 * quad]       = ulo;
            *(uint2*)&Psm[(size_t)(rl + 8) * PS_STR + j * 8 + 2 * quad] = uhi;
        }
        rs_lo += __shfl_xor_sync(0xffffffffu, rs_lo, 1);
        rs_lo += __shfl_xor_sync(0xffffffffu, rs_lo, 2);
        rs_hi += __shfl_xor_sync(0xffffffffu, rs_hi, 1);
        rs_hi += __shfl_xor_sync(0xffffffffu, rs_hi, 2);
        l_lo = l_lo * al_lo + rs_lo;
        l_hi = l_hi * al_hi + rs_hi;

        __syncwarp();   // P rows are warp-local; order STS before LDS

        // ---- O += P V ----
        #pragma unroll
        for (int kc = 0; kc < 16; kc++) {
            const int kk = kc * 8 + quad;
            unsigned a[4];
            a[0] = Psm[(size_t)rl * PS_STR + kk];
            a[1] = Psm[(size_t)(rl + 8) * PS_STR + kk];
            a[2] = Psm[(size_t)rl * PS_STR + kk + 4];
            a[3] = Psm[(size_t)(rl + 8) * PS_STR + kk + 4];
            const unsigned* Vpp = &Vp[(kc * 4 + quad) * VPL];
            #pragma unroll
            for (int n = 0; n < 8; n++) {
                uint2 ub = *(const uint2*)&Vpp[(n * 8 + qrl) * 2];
                mma_tf32(o[n], a, ub.x, ub.y);
            }
        }
        __syncthreads();  // done with Kp/Vp before next tile load
    }

    // ---- epilogue ----
    const float inv_lo = 1.0f / l_lo;
    const float inv_hi = 1.0f / l_hi;
    const int rl = q0 + w * 16 + qrl;
    #pragma unroll
    for (int n = 0; n < 8; n++) {
        int col = h * HDIM + n * 8 + 2 * quad;
        float2 vlo = make_float2(o[n][0] * inv_lo, o[n][1] * inv_lo);
        float2 vhi = make_float2(o[n][2] * inv_hi, o[n][3] * inv_hi);
        *(float2*)&g_att[(size_t)rl * CC + col]       = vlo;
        *(float2*)&g_att[(size_t)(rl + 8) * CC + col] = vhi;
    }
}

// ---------------------------------------------------------------------------
// Launch
// ---------------------------------------------------------------------------
extern "C" void kernel_launch(void* const* d_in, const int* in_sizes, int n_in,
                              void* d_out, int out_size)
{
    const float* x      = (const float*)d_in[0];
    const float* W_attn = (const float*)d_in[1];
    const float* b_attn = (const float*)d_in[2];
    const float* W_proj = (const float*)d_in[3];
    const float* b_proj = (const float*)d_in[4];
    float*       out    = (float*)d_out;

    void *qkv_p, *att_p;
    cudaGetSymbolAddress(&qkv_p, g_qkv);
    cudaGetSymbolAddress(&att_p, g_att);
    float* qkv = (float*)qkv_p;
    float* att = (float*)att_p;

    const int FLASH_SMEM =
        (HDIM * QS_STR + 32 * KPL + 64 * VPL + 128 * PS_STR) * (int)sizeof(unsigned);
    cudaFuncSetAttribute(flash_attn_tc,
                         cudaFuncAttributeMaxDynamicSharedMemorySize, FLASH_SMEM);

    // 1) QKV projection
    {
        dim3 grid(3 * CC / 128, TT / 128);
        gemm_tc<<<grid, 256>>>(x, W_attn, b_attn, qkv, TT, 3 * CC, CC);
    }
    // 2) Causal flash attention
    {
        dim3 grid(TT / 128, NHEAD);
        flash_attn_tc<<<grid, 256, FLASH_SMEM>>>();
    }
    // 3) Output projection
    {
        dim3 grid(CC / 128, TT / 128);
        gemm_tc<<<grid, 256>>>(att, W_proj, b_proj, out, TT, CC, CC);
    }
}

// round 8
// speedup vs baseline: 1.2292x; 1.2292x over previous
#include <cuda_runtime.h>
#include <cuda_bf16.h>
#include <cstdint>
#include <math.h>

// ---------------------------------------------------------------------------
// GPT2 attention block — tf32 mma.sync, ldmatrix + cp.async GEMMs.
//   prepass: round x, round+transpose weights (tf32-exact operands)
//   x @ W_attn + b_attn -> qkv          (gemm_tc: cp.async + ldmatrix)
//   16-head causal flash attention      -> att (rounded)
//   att @ W_proj + b_proj -> out        (gemm_tc)
// ---------------------------------------------------------------------------

#define TT      4096
#define CC      1024
#define NHEAD   16
#define HDIM    64
#define SCALE   0.125f

__device__ float g_qkv[TT * 3 * CC];
__device__ float g_att[TT * CC];        // rounded by attention epilogue
__device__ float g_xr [TT * CC];        // rna-rounded x
__device__ float g_wat[3 * CC * CC];    // W_attn^T [3072][1024], rounded
__device__ float g_wpt[CC * CC];        // W_proj^T [1024][1024], rounded

// ============================ helpers ======================================
__device__ __forceinline__ uint32_t smem_u32(const void* p) {
    uint32_t a;
    asm("{ .reg .u64 t; cvta.to.shared.u64 t, %1; cvt.u32.u64 %0, t; }"
        : "=r"(a) : "l"(p));
    return a;
}
__device__ __forceinline__ unsigned cvt_tf32(float x) {
    unsigned u;
    asm("cvt.rna.tf32.f32 %0, %1;" : "=r"(u) : "f"(x));
    return u;
}
__device__ __forceinline__ float tf32r(float x) {
    return __uint_as_float(cvt_tf32(x));
}
__device__ __forceinline__ void mma_tf32(float* d, const unsigned* a,
                                         unsigned b0, unsigned b1) {
    asm volatile(
        "mma.sync.aligned.m16n8k8.row.col.f32.tf32.tf32.f32 "
        "{%0,%1,%2,%3}, {%4,%5,%6,%7}, {%8,%9}, {%0,%1,%2,%3};"
        : "+f"(d[0]), "+f"(d[1]), "+f"(d[2]), "+f"(d[3])
        : "r"(a[0]), "r"(a[1]), "r"(a[2]), "r"(a[3]), "r"(b0), "r"(b1));
}
__device__ __forceinline__ void ldsm4(unsigned* r, uint32_t addr) {
    asm volatile("ldmatrix.sync.aligned.m8n8.x4.shared.b16 {%0,%1,%2,%3}, [%4];"
                 : "=r"(r[0]), "=r"(r[1]), "=r"(r[2]), "=r"(r[3]) : "r"(addr));
}
__device__ __forceinline__ void cpa16(uint32_t dst, const float* src) {
    asm volatile("cp.async.cg.shared.global [%0], [%1], 16;" :: "r"(dst), "l"(src));
}
#define CP_COMMIT() asm volatile("cp.async.commit_group;" ::: "memory")
#define CP_WAIT1()  asm volatile("cp.async.wait_group 1;" ::: "memory")

// ============================ pre-pass kernels =============================
__global__ void round_copy(const float* __restrict__ in, float* __restrict__ out, int n4) {
    int i = blockIdx.x * blockDim.x + threadIdx.x;
    if (i < n4) {
        float4 v = ((const float4*)in)[i];
        v.x = tf32r(v.x); v.y = tf32r(v.y); v.z = tf32r(v.z); v.w = tf32r(v.w);
        ((float4*)out)[i] = v;
    }
}

// W[K][N] -> Wt[N][K], rna-rounded. grid (N/32, K/32), block (32,8).
__global__ void transpose_round(const float* __restrict__ W, float* __restrict__ Wt,
                                int K, int N) {
    __shared__ float t[32][33];
    int n0 = blockIdx.x * 32, k0 = blockIdx.y * 32;
    int tx = threadIdx.x, ty = threadIdx.y;
    #pragma unroll
    for (int j = 0; j < 32; j += 8)
        t[ty + j][tx] = W[(size_t)(k0 + ty + j) * N + n0 + tx];
    __syncthreads();
    #pragma unroll
    for (int j = 0; j < 32; j += 8)
        Wt[(size_t)(n0 + ty + j) * K + k0 + tx] = tf32r(t[tx][ty + j]);
}

// ============================ GEMM =========================================
// C[M,N] = A[M,K] @ Bt[N,K]^T + bias.  A, Bt hold tf32-exact fp32 values.
// Block 128x128, BK=32, 256 threads = 8 warps (2x4 -> warp tile 64x32).
// Staging: cp.async 16B chunks, chunk XOR-swizzled by (row&7), 2 slots.
// Fragments: ldmatrix.x4 (tf32-as-b16 trick).
#define GEMM_SMEM 65536

__global__ __launch_bounds__(256, 2)
void gemm_tc(const float* __restrict__ A, const float* __restrict__ Bt,
             const float* __restrict__ bias, float* __restrict__ C,
             int M, int N, int K)
{
    extern __shared__ char dsm[];
    const uint32_t sb = smem_u32(dsm);

    const int tid  = threadIdx.x;
    const int lane = tid & 31;
    const int qrl  = lane >> 2;
    const int quad = lane & 3;
    const int w    = tid >> 5;
    const int wm   = w >> 2;          // 0..1
    const int wn   = w & 3;           // 0..3
    const int bm   = blockIdx.y * 128;
    const int bn   = blockIdx.x * 128;

    float d[4][4][4];
    #pragma unroll
    for (int im = 0; im < 4; im++)
        #pragma unroll
        for (int jn = 0; jn < 4; jn++)
            #pragma unroll
            for (int r = 0; r < 4; r++) d[im][jn][r] = 0.0f;

    // staging assignment: thread -> row r (0..127), chunks c0..c0+3 (of 8)
    const int r  = tid >> 1;
    const int c0 = (tid & 1) * 4;
    const float* gA = A  + (size_t)(bm + r) * K;
    const float* gB = Bt + (size_t)(bn + r) * K;
    const uint32_t rowoff = (uint32_t)r * 128u;
    const int rx = r & 7;

    const int NST = K / 32;

    // prologue: stage 0 into slot 0
    #pragma unroll
    for (int i = 0; i < 4; i++) {
        int c = c0 + i;
        uint32_t doff = rowoff + (uint32_t)((c ^ rx) << 4);
        cpa16(sb + doff,          gA + c * 4);
        cpa16(sb + 16384 + doff,  gB + c * 4);
    }
    CP_COMMIT();

    const int mtx = lane >> 3;        // ldmatrix matrix id
    const int rr  = lane & 7;         // row within matrix

    for (int s = 0; s < NST; s++) {
        // issue stage s+1 into the other slot (or empty commit at tail)
        if (s + 1 < NST) {
            const uint32_t slot = (uint32_t)((s + 1) & 1) * 32768u;
            const int k0 = (s + 1) * 32;
            #pragma unroll
            for (int i = 0; i < 4; i++) {
                int c = c0 + i;
                uint32_t doff = slot + rowoff + (uint32_t)((c ^ rx) << 4);
                cpa16(sb + doff,         gA + k0 + c * 4);
                cpa16(sb + 16384 + doff, gB + k0 + c * 4);
            }
        }
        CP_COMMIT();
        CP_WAIT1();           // stage s complete (<=1 group pending)
        __syncthreads();

        const uint32_t Ab = sb + (uint32_t)(s & 1) * 32768u;
        const uint32_t Bb = Ab + 16384u;

        #pragma unroll
        for (int ks = 0; ks < 4; ks++) {
            // A fragments: 4 x ldmatrix.x4 (each = 16m x 8k)
            unsigned a[4][4];
            #pragma unroll
            for (int im = 0; im < 4; im++) {
                int m_row = wm * 64 + im * 16 + rr + ((mtx & 1) << 3);
                int kch   = ks * 2 + (mtx >> 1);
                uint32_t addr = Ab + (uint32_t)m_row * 128u
                              + (uint32_t)((kch ^ (m_row & 7)) << 4);
                ldsm4(a[im], addr);
            }
            // B fragments: 2 x ldmatrix.x4 (each = 16n x 8k -> two n8-tiles)
            unsigned b[2][4];
            #pragma unroll
            for (int j2 = 0; j2 < 2; j2++) {
                int n_row = wn * 32 + j2 * 16 + rr + ((mtx >> 1) << 3);
                int kch   = ks * 2 + (mtx & 1);
                uint32_t addr = Bb + (uint32_t)n_row * 128u
                              + (uint32_t)((kch ^ (n_row & 7)) << 4);
                ldsm4(b[j2], addr);
            }
            #pragma unroll
            for (int im = 0; im < 4; im++)
                #pragma unroll
                for (int jn = 0; jn < 4; jn++)
                    mma_tf32(d[im][jn], a[im],
                             b[jn >> 1][(jn & 1) * 2],
                             b[jn >> 1][(jn & 1) * 2 + 1]);
        }
        __syncthreads();      // compute done before slot reuse next iter
    }

    // ---- epilogue + bias ----
    #pragma unroll
    for (int im = 0; im < 4; im++) {
        int r_lo = bm + wm * 64 + im * 16 + qrl;
        #pragma unroll
        for (int jn = 0; jn < 4; jn++) {
            int col = bn + wn * 32 + jn * 8 + 2 * quad;
            float b0 = bias[col], b1 = bias[col + 1];
            float2 v0 = make_float2(d[im][jn][0] + b0, d[im][jn][1] + b1);
            float2 v1 = make_float2(d[im][jn][2] + b0, d[im][jn][3] + b1);
            *(float2*)&C[(size_t)r_lo * N + col]       = v0;
            *(float2*)&C[(size_t)(r_lo + 8) * N + col] = v1;
        }
    }
}

// ---------------------------------------------------------------------------
// Tensor-core causal flash attention (round-7 layouts, rounded output).
// ---------------------------------------------------------------------------
#define QS_STR 132
#define KPL    264
#define VPL    136
#define PS_STR 132

__global__ __launch_bounds__(256)
void flash_attn_tc()
{
    extern __shared__ unsigned smem[];
    unsigned* Qs  = smem;                    // [64][132]  Q^T (tf32)
    unsigned* Kp  = Qs + HDIM * QS_STR;      // 32 planes x 264
    unsigned* Vp  = Kp + 32 * KPL;           // 64 planes x 136
    unsigned* Psm = Vp + 64 * VPL;           // [128][132] P (tf32)

    const int h    = blockIdx.y;
    const int qt   = (int)gridDim.x - 1 - (int)blockIdx.x;  // heavy first
    const int q0   = qt * 128;
    const int tid  = threadIdx.x;
    const int lane = tid & 31;
    const int w    = tid >> 5;
    const int qrl  = lane >> 2;
    const int quad = lane & 3;

    #pragma unroll
    for (int i = 0; i < 8; i++) {
        int idx = tid + i * 256;
        int rr  = idx >> 4;
        int c4  = (idx & 15) * 4;
        float4 v = *(const float4*)&g_qkv[(size_t)(q0 + rr) * (3 * CC) + h * HDIM + c4];
        Qs[(c4 + 0) * QS_STR + rr] = cvt_tf32(v.x);
        Qs[(c4 + 1) * QS_STR + rr] = cvt_tf32(v.y);
        Qs[(c4 + 2) * QS_STR + rr] = cvt_tf32(v.z);
        Qs[(c4 + 3) * QS_STR + rr] = cvt_tf32(v.w);
    }

    float o[8][4];
    #pragma unroll
    for (int n = 0; n < 8; n++)
        #pragma unroll
        for (int r = 0; r < 4; r++) o[n][r] = 0.0f;
    float m_lo = -1e30f, m_hi = -1e30f, l_lo = 0.0f, l_hi = 0.0f;

    for (int kt = 0; kt <= qt; kt++) {
        const int k0 = kt * 128;

        #pragma unroll
        for (int i = 0; i < 8; i++) {
            int idx = tid + i * 256;
            int rr  = idx >> 4;
            int c4  = (idx & 15) * 4;
            const float* kro = &g_qkv[(size_t)(k0 + rr) * (3 * CC) + CC + h * HDIM + c4];
            float4 kv = *(const float4*)kro;
            {
                int ks = c4 >> 3, half = (c4 >> 2) & 1;
                unsigned* p = &Kp[(ks * 4) * KPL + rr * 2 + half];
                p[0 * KPL] = cvt_tf32(kv.x);
                p[1 * KPL] = cvt_tf32(kv.y);
                p[2 * KPL] = cvt_tf32(kv.z);
                p[3 * KPL] = cvt_tf32(kv.w);
            }
            float4 vv = *(const float4*)(kro + CC);
            {
                int kc = rr >> 3, r8 = rr & 7;
                unsigned* p = &Vp[(kc * 4 + (r8 & 3)) * VPL + c4 * 2 + (r8 >> 2)];
                p[0] = cvt_tf32(vv.x);
                p[2] = cvt_tf32(vv.y);
                p[4] = cvt_tf32(vv.z);
                p[6] = cvt_tf32(vv.w);
            }
        }
        __syncthreads();

        float s[16][4];
        #pragma unroll
        for (int j = 0; j < 16; j++)
            #pragma unroll
            for (int r = 0; r < 4; r++) s[j][r] = 0.0f;

        #pragma unroll
        for (int ks = 0; ks < 8; ks++) {
            const int kk = ks * 8 + quad;
            unsigned a[4];
            a[0] = Qs[kk * QS_STR + w * 16 + qrl];
            a[1] = Qs[kk * QS_STR + w * 16 + qrl + 8];
            a[2] = Qs[(kk + 4) * QS_STR + w * 16 + qrl];
            a[3] = Qs[(kk + 4) * QS_STR + w * 16 + qrl + 8];
            const unsigned* Kpp = &Kp[(ks * 4 + quad) * KPL];
            #pragma unroll
            for (int j = 0; j < 16; j++) {
                uint2 ub = *(const uint2*)&Kpp[(j * 8 + qrl) * 2];
                mma_tf32(s[j], a, ub.x, ub.y);
            }
        }

        float tm_lo = -1e30f, tm_hi = -1e30f;
        #pragma unroll
        for (int j = 0; j < 16; j++) {
            #pragma unroll
            for (int r = 0; r < 4; r++) s[j][r] *= SCALE;
            if (kt == qt) {
                int col = j * 8 + 2 * quad;
                int rl  = w * 16 + qrl;
                int rh  = rl + 8;
                if (col > rl)     s[j][0] = -1e30f;
                if (col + 1 > rl) s[j][1] = -1e30f;
                if (col > rh)     s[j][2] = -1e30f;
                if (col + 1 > rh) s[j][3] = -1e30f;
            }
            tm_lo = fmaxf(tm_lo, fmaxf(s[j][0], s[j][1]));
            tm_hi = fmaxf(tm_hi, fmaxf(s[j][2], s[j][3]));
        }
        tm_lo = fmaxf(tm_lo, __shfl_xor_sync(0xffffffffu, tm_lo, 1));
        tm_lo = fmaxf(tm_lo, __shfl_xor_sync(0xffffffffu, tm_lo, 2));
        tm_hi = fmaxf(tm_hi, __shfl_xor_sync(0xffffffffu, tm_hi, 1));
        tm_hi = fmaxf(tm_hi, __shfl_xor_sync(0xffffffffu, tm_hi, 2));

        float mn_lo = fmaxf(m_lo, tm_lo);
        float mn_hi = fmaxf(m_hi, tm_hi);
        float al_lo = __expf(m_lo - mn_lo);
        float al_hi = __expf(m_hi - mn_hi);
        m_lo = mn_lo; m_hi = mn_hi;
        #pragma unroll
        for (int n = 0; n < 8; n++) {
            o[n][0] *= al_lo; o[n][1] *= al_lo;
            o[n][2] *= al_hi; o[n][3] *= al_hi;
        }

        float rs_lo = 0.0f, rs_hi = 0.0f;
        const int rl = w * 16 + qrl;
        #pragma unroll
        for (int j = 0; j < 16; j++) {
            float p0 = __expf(s[j][0] - mn_lo);
            float p1 = __expf(s[j][1] - mn_lo);
            float p2 = __expf(s[j][2] - mn_hi);
            float p3 = __expf(s[j][3] - mn_hi);
            rs_lo += p0 + p1;
            rs_hi += p2 + p3;
            uint2 ulo = make_uint2(cvt_tf32(p0), cvt_tf32(p1));
            uint2 uhi = make_uint2(cvt_tf32(p2), cvt_tf32(p3));
            *(uint2*)&Psm[(size_t)rl * PS_STR + j * 8 + 2 * quad]       = ulo;
            *(uint2*)&Psm[(size_t)(rl + 8) * PS_STR + j * 8 + 2 * quad] = uhi;
        }
        rs_lo += __shfl_xor_sync(0xffffffffu, rs_lo, 1);
        rs_lo += __shfl_xor_sync(0xffffffffu, rs_lo, 2);
        rs_hi += __shfl_xor_sync(0xffffffffu, rs_hi, 1);
        rs_hi += __shfl_xor_sync(0xffffffffu, rs_hi, 2);
        l_lo = l_lo * al_lo + rs_lo;
        l_hi = l_hi * al_hi + rs_hi;

        __syncwarp();

        #pragma unroll
        for (int kc = 0; kc < 16; kc++) {
            const int kk = kc * 8 + quad;
            unsigned a[4];
            a[0] = Psm[(size_t)rl * PS_STR + kk];
            a[1] = Psm[(size_t)(rl + 8) * PS_STR + kk];
            a[2] = Psm[(size_t)rl * PS_STR + kk + 4];
            a[3] = Psm[(size_t)(rl + 8) * PS_STR + kk + 4];
            const unsigned* Vpp = &Vp[(kc * 4 + quad) * VPL];
            #pragma unroll
            for (int n = 0; n < 8; n++) {
                uint2 ub = *(const uint2*)&Vpp[(n * 8 + qrl) * 2];
                mma_tf32(o[n], a, ub.x, ub.y);
            }
        }
        __syncthreads();
    }

    // epilogue: normalize + rna-round (att feeds the tf32 proj GEMM)
    const float inv_lo = 1.0f / l_lo;
    const float inv_hi = 1.0f / l_hi;
    const int rl = q0 + w * 16 + qrl;
    #pragma unroll
    for (int n = 0; n < 8; n++) {
        int col = h * HDIM + n * 8 + 2 * quad;
        float2 vlo = make_float2(tf32r(o[n][0] * inv_lo), tf32r(o[n][1] * inv_lo));
        float2 vhi = make_float2(tf32r(o[n][2] * inv_hi), tf32r(o[n][3] * inv_hi));
        *(float2*)&g_att[(size_t)rl * CC + col]       = vlo;
        *(float2*)&g_att[(size_t)(rl + 8) * CC + col] = vhi;
    }
}

// ================================ launch ===================================
extern "C" void kernel_launch(void* const* d_in, const int* in_sizes, int n_in,
                              void* d_out, int out_size)
{
    const float* x      = (const float*)d_in[0];
    const float* W_attn = (const float*)d_in[1];
    const float* b_attn = (const float*)d_in[2];
    const float* W_proj = (const float*)d_in[3];
    const float* b_proj = (const float*)d_in[4];
    float*       out    = (float*)d_out;

    void *qkv_p, *att_p, *xr_p, *wat_p, *wpt_p;
    cudaGetSymbolAddress(&qkv_p, g_qkv);
    cudaGetSymbolAddress(&att_p, g_att);
    cudaGetSymbolAddress(&xr_p,  g_xr);
    cudaGetSymbolAddress(&wat_p, g_wat);
    cudaGetSymbolAddress(&wpt_p, g_wpt);
    float* qkv = (float*)qkv_p;
    float* att = (float*)att_p;
    float* xr  = (float*)xr_p;
    float* wat = (float*)wat_p;
    float* wpt = (float*)wpt_p;

    const int FLASH_SMEM =
        (HDIM * QS_STR + 32 * KPL + 64 * VPL + 128 * PS_STR) * (int)sizeof(unsigned);
    cudaFuncSetAttribute(flash_attn_tc,
                         cudaFuncAttributeMaxDynamicSharedMemorySize, FLASH_SMEM);
    cudaFuncSetAttribute(gemm_tc,
                         cudaFuncAttributeMaxDynamicSharedMemorySize, GEMM_SMEM);

    // 0) pre-pass: round x; transpose+round weights
    {
        int n4 = TT * CC / 4;
        round_copy<<<(n4 + 255) / 256, 256>>>(x, xr, n4);
        transpose_round<<<dim3(3 * CC / 32, CC / 32), dim3(32, 8)>>>(W_attn, wat, CC, 3 * CC);
        transpose_round<<<dim3(CC / 32, CC / 32), dim3(32, 8)>>>(W_proj, wpt, CC, CC);
    }
    // 1) QKV projection
    {
        dim3 grid(3 * CC / 128, TT / 128);
        gemm_tc<<<grid, 256, GEMM_SMEM>>>(xr, wat, b_attn, qkv, TT, 3 * CC, CC);
    }
    // 2) Causal flash attention
    {
        dim3 grid(TT / 128, NHEAD);
        flash_attn_tc<<<grid, 256, FLASH_SMEM>>>();
    }
    // 3) Output projection
    {
        dim3 grid(CC / 128, TT / 128);
        gemm_tc<<<grid, 256, GEMM_SMEM>>>(att, wpt, b_proj, out, TT, CC, CC);
    }
}

// round 9
// speedup vs baseline: 1.3918x; 1.1322x over previous
#include <cuda_runtime.h>
#include <cuda_bf16.h>
#include <cstdint>
#include <math.h>

// ---------------------------------------------------------------------------
// GPT2 attention block — tf32 mma.sync.
//   prepass: round x, round+transpose weights
//   x @ W_attn + b_attn -> qkv (rounded)   [gemm_tc: 3-stage cp.async+ldmatrix]
//   flash attention BQ=256/BKV=64, Q in registers, cp.async K/V  -> att (rounded)
//   att @ W_proj + b_proj -> out           [gemm_tc]
// ---------------------------------------------------------------------------

#define TT      4096
#define CC      1024
#define NHEAD   16
#define HDIM    64
#define SCALE   0.125f

__device__ float g_qkv[TT * 3 * CC];
__device__ float g_att[TT * CC];
__device__ float g_xr [TT * CC];
__device__ float g_wat[3 * CC * CC];
__device__ float g_wpt[CC * CC];

// ============================ helpers ======================================
__device__ __forceinline__ uint32_t smem_u32(const void* p) {
    uint32_t a;
    asm("{ .reg .u64 t; cvta.to.shared.u64 t, %1; cvt.u32.u64 %0, t; }"
        : "=r"(a) : "l"(p));
    return a;
}
__device__ __forceinline__ unsigned cvt_tf32(float x) {
    unsigned u;
    asm("cvt.rna.tf32.f32 %0, %1;" : "=r"(u) : "f"(x));
    return u;
}
__device__ __forceinline__ float tf32r(float x) {
    return __uint_as_float(cvt_tf32(x));
}
__device__ __forceinline__ void mma_tf32(float* d, const unsigned* a,
                                         unsigned b0, unsigned b1) {
    asm volatile(
        "mma.sync.aligned.m16n8k8.row.col.f32.tf32.tf32.f32 "
        "{%0,%1,%2,%3}, {%4,%5,%6,%7}, {%8,%9}, {%0,%1,%2,%3};"
        : "+f"(d[0]), "+f"(d[1]), "+f"(d[2]), "+f"(d[3])
        : "r"(a[0]), "r"(a[1]), "r"(a[2]), "r"(a[3]), "r"(b0), "r"(b1));
}
__device__ __forceinline__ void ldsm4(unsigned* r, uint32_t addr) {
    asm volatile("ldmatrix.sync.aligned.m8n8.x4.shared.b16 {%0,%1,%2,%3}, [%4];"
                 : "=r"(r[0]), "=r"(r[1]), "=r"(r[2]), "=r"(r[3]) : "r"(addr));
}
__device__ __forceinline__ void cpa16(uint32_t dst, const float* src) {
    asm volatile("cp.async.cg.shared.global [%0], [%1], 16;" :: "r"(dst), "l"(src));
}
#define CP_COMMIT() asm volatile("cp.async.commit_group;" ::: "memory")
#define CP_WAIT1()  asm volatile("cp.async.wait_group 1;" ::: "memory")
#define CP_WAIT2()  asm volatile("cp.async.wait_group 2;" ::: "memory")

// ============================ pre-pass kernels =============================
__global__ void round_copy(const float* __restrict__ in, float* __restrict__ out, int n4) {
    int i = blockIdx.x * blockDim.x + threadIdx.x;
    if (i < n4) {
        float4 v = ((const float4*)in)[i];
        v.x = tf32r(v.x); v.y = tf32r(v.y); v.z = tf32r(v.z); v.w = tf32r(v.w);
        ((float4*)out)[i] = v;
    }
}
__global__ void transpose_round(const float* __restrict__ W, float* __restrict__ Wt,
                                int K, int N) {
    __shared__ float t[32][33];
    int n0 = blockIdx.x * 32, k0 = blockIdx.y * 32;
    int tx = threadIdx.x, ty = threadIdx.y;
    #pragma unroll
    for (int j = 0; j < 32; j += 8)
        t[ty + j][tx] = W[(size_t)(k0 + ty + j) * N + n0 + tx];
    __syncthreads();
    #pragma unroll
    for (int j = 0; j < 32; j += 8)
        Wt[(size_t)(n0 + ty + j) * K + k0 + tx] = tf32r(t[tx][ty + j]);
}

// ============================ GEMM =========================================
// C[M,N] = A[M,K] @ Bt[N,K]^T + bias. 3-stage cp.async + ldmatrix fragments.
#define GEMM_SMEM (3 * 32768)

__global__ __launch_bounds__(256, 2)
void gemm_tc(const float* __restrict__ A, const float* __restrict__ Bt,
             const float* __restrict__ bias, float* __restrict__ C,
             int M, int N, int K, int round_out)
{
    extern __shared__ char dsm[];
    const uint32_t sb = smem_u32(dsm);

    const int tid  = threadIdx.x;
    const int lane = tid & 31;
    const int qrl  = lane >> 2;
    const int quad = lane & 3;
    const int w    = tid >> 5;
    const int wm   = w >> 2;
    const int wn   = w & 3;
    const int bm   = blockIdx.y * 128;
    const int bn   = blockIdx.x * 128;

    float d[4][4][4];
    #pragma unroll
    for (int im = 0; im < 4; im++)
        #pragma unroll
        for (int jn = 0; jn < 4; jn++)
            #pragma unroll
            for (int r = 0; r < 4; r++) d[im][jn][r] = 0.0f;

    const int r  = tid >> 1;
    const int c0 = (tid & 1) * 4;
    const float* gA = A  + (size_t)(bm + r) * K;
    const float* gB = Bt + (size_t)(bn + r) * K;
    const uint32_t rowoff = (uint32_t)r * 128u;
    const int rx = r & 7;

    const int NST = K / 32;

    // prologue: stages 0 and 1
    #pragma unroll
    for (int st = 0; st < 2; st++) {
        const uint32_t slot = (uint32_t)st * 32768u;
        #pragma unroll
        for (int i = 0; i < 4; i++) {
            int c = c0 + i;
            uint32_t doff = slot + rowoff + (uint32_t)((c ^ rx) << 4);
            cpa16(sb + doff,          gA + st * 32 + c * 4);
            cpa16(sb + 16384 + doff,  gB + st * 32 + c * 4);
        }
        CP_COMMIT();
    }

    const int mtx = lane >> 3;
    const int rr  = lane & 7;

    for (int s = 0; s < NST; s++) {
        if (s + 2 < NST) {
            const uint32_t slot = (uint32_t)((s + 2) % 3) * 32768u;
            const int k0 = (s + 2) * 32;
            #pragma unroll
            for (int i = 0; i < 4; i++) {
                int c = c0 + i;
                uint32_t doff = slot + rowoff + (uint32_t)((c ^ rx) << 4);
                cpa16(sb + doff,         gA + k0 + c * 4);
                cpa16(sb + 16384 + doff, gB + k0 + c * 4);
            }
        }
        CP_COMMIT();
        CP_WAIT2();
        __syncthreads();

        const uint32_t Ab = sb + (uint32_t)(s % 3) * 32768u;
        const uint32_t Bb = Ab + 16384u;

        #pragma unroll
        for (int ks = 0; ks < 4; ks++) {
            unsigned a[4][4];
            #pragma unroll
            for (int im = 0; im < 4; im++) {
                int m_row = wm * 64 + im * 16 + rr + ((mtx & 1) << 3);
                int kch   = ks * 2 + (mtx >> 1);
                uint32_t addr = Ab + (uint32_t)m_row * 128u
                              + (uint32_t)((kch ^ (m_row & 7)) << 4);
                ldsm4(a[im], addr);
            }
            unsigned b[2][4];
            #pragma unroll
            for (int j2 = 0; j2 < 2; j2++) {
                int n_row = wn * 32 + j2 * 16 + rr + ((mtx >> 1) << 3);
                int kch   = ks * 2 + (mtx & 1);
                uint32_t addr = Bb + (uint32_t)n_row * 128u
                              + (uint32_t)((kch ^ (n_row & 7)) << 4);
                ldsm4(b[j2], addr);
            }
            #pragma unroll
            for (int im = 0; im < 4; im++)
                #pragma unroll
                for (int jn = 0; jn < 4; jn++)
                    mma_tf32(d[im][jn], a[im],
                             b[jn >> 1][(jn & 1) * 2],
                             b[jn >> 1][(jn & 1) * 2 + 1]);
        }
        __syncthreads();
    }

    #pragma unroll
    for (int im = 0; im < 4; im++) {
        int r_lo = bm + wm * 64 + im * 16 + qrl;
        #pragma unroll
        for (int jn = 0; jn < 4; jn++) {
            int col = bn + wn * 32 + jn * 8 + 2 * quad;
            float b0 = bias[col], b1 = bias[col + 1];
            float2 v0, v1;
            if (round_out) {
                v0 = make_float2(tf32r(d[im][jn][0] + b0), tf32r(d[im][jn][1] + b1));
                v1 = make_float2(tf32r(d[im][jn][2] + b0), tf32r(d[im][jn][3] + b1));
            } else {
                v0 = make_float2(d[im][jn][0] + b0, d[im][jn][1] + b1);
                v1 = make_float2(d[im][jn][2] + b0, d[im][jn][3] + b1);
            }
            *(float2*)&C[(size_t)r_lo * N + col]       = v0;
            *(float2*)&C[(size_t)(r_lo + 8) * N + col] = v1;
        }
    }
}

// ============================ flash attention ==============================
// BQ=256 q rows/block, BKV=64 keys/tile, 8 warps x 32 q rows (2 m-tiles).
// Q in registers (loaded once). K/V cp.async double-buffered row-major
// swizzled tiles. P through smem (warp-local). qkv is tf32-pre-rounded.
#define PSTR 68
#define ATT_SMEM (65536 + 256 * PSTR * 4)   // K(2x16K) V(2x16K) + P

__device__ __forceinline__ void att_stage(uint32_t sb, int tid, int h, int kt) {
    const uint32_t kslot = sb + (uint32_t)(kt & 1) * 16384u;
    const uint32_t vslot = sb + 32768u + (uint32_t)(kt & 1) * 16384u;
    const int k0 = kt * 64;
    #pragma unroll
    for (int i = 0; i < 4; i++) {
        int idx = tid + i * 256;
        int r = idx >> 4, c = idx & 15;
        const float* src = &g_qkv[(size_t)(k0 + r) * (3 * CC) + CC + h * HDIM + c * 4];
        uint32_t doff = (uint32_t)r * 256u + (uint32_t)((c ^ (r & 7)) << 4);
        cpa16(kslot + doff, src);
        cpa16(vslot + doff, src + CC);
    }
}

__global__ __launch_bounds__(256)
void flash_attn_tc()
{
    extern __shared__ char asmem[];
    const uint32_t sb = smem_u32(asmem);
    float* Psm = (float*)(asmem + 65536);

    const int h    = blockIdx.y;
    const int qt   = 15 - (int)blockIdx.x;   // heavy first
    const int q0   = qt * 256;
    const int tid  = threadIdx.x;
    const int lane = tid & 31;
    const int w    = tid >> 5;
    const int qrl  = lane >> 2;
    const int quad = lane & 3;

    // ---- Q fragments in registers (qkv pre-rounded to tf32 values) ----
    unsigned qa[2][8][4];
    #pragma unroll
    for (int im = 0; im < 2; im++) {
        int row = q0 + w * 32 + im * 16 + qrl;
        const float* p0 = &g_qkv[(size_t)row * (3 * CC) + h * HDIM + quad];
        const float* p1 = p0 + (size_t)8 * (3 * CC);
        #pragma unroll
        for (int ks = 0; ks < 8; ks++) {
            qa[im][ks][0] = __float_as_uint(p0[ks * 8]);
            qa[im][ks][1] = __float_as_uint(p1[ks * 8]);
            qa[im][ks][2] = __float_as_uint(p0[ks * 8 + 4]);
            qa[im][ks][3] = __float_as_uint(p1[ks * 8 + 4]);
        }
    }

    float o[2][8][4];
    #pragma unroll
    for (int im = 0; im < 2; im++)
        #pragma unroll
        for (int n = 0; n < 8; n++)
            #pragma unroll
            for (int r = 0; r < 4; r++) o[im][n][r] = 0.0f;
    float mm[2][2] = {{-1e30f, -1e30f}, {-1e30f, -1e30f}};
    float ll[2][2] = {{0.0f, 0.0f}, {0.0f, 0.0f}};

    const int n_tiles = 4 * (qt + 1);

    att_stage(sb, tid, h, 0);
    CP_COMMIT();

    for (int kt = 0; kt < n_tiles; kt++) {
        if (kt + 1 < n_tiles) att_stage(sb, tid, h, kt + 1);
        CP_COMMIT();
        CP_WAIT1();
        __syncthreads();

        const float* Ks = (const float*)(asmem + (kt & 1) * 16384);
        const float* Vs = (const float*)(asmem + 32768 + (kt & 1) * 16384);
        const int k0 = kt * 64;
        const bool active = (k0 < q0 + w * 32 + 32);

        if (active) {
            // ---- S = Q K^T ----
            float s[2][8][4];
            #pragma unroll
            for (int im = 0; im < 2; im++)
                #pragma unroll
                for (int j = 0; j < 8; j++)
                    #pragma unroll
                    for (int r = 0; r < 4; r++) s[im][j][r] = 0.0f;

            #pragma unroll
            for (int ks = 0; ks < 8; ks++) {
                #pragma unroll
                for (int j = 0; j < 8; j++) {
                    int row = j * 8 + qrl;
                    const float* rp = Ks + row * 64;
                    unsigned b0 = __float_as_uint(rp[(((2 * ks)     ^ (row & 7)) << 2) + quad]);
                    unsigned b1 = __float_as_uint(rp[(((2 * ks + 1) ^ (row & 7)) << 2) + quad]);
                    mma_tf32(s[0][j], qa[0][ks], b0, b1);
                    mma_tf32(s[1][j], qa[1][ks], b0, b1);
                }
            }

            // ---- softmax per m-tile ----
            #pragma unroll
            for (int im = 0; im < 2; im++) {
                const int base   = q0 + w * 32 + im * 16;
                const int row_lo = base + qrl;
                const bool domask = (k0 + 63 > base);   // uniform per (warp,im)
                float tml = -1e30f, tmh = -1e30f;
                #pragma unroll
                for (int j = 0; j < 8; j++) {
                    #pragma unroll
                    for (int r2 = 0; r2 < 4; r2++) s[im][j][r2] *= SCALE;
                    if (domask) {
                        int col = k0 + j * 8 + 2 * quad;
                        if (col     > row_lo)     s[im][j][0] = -1e30f;
                        if (col + 1 > row_lo)     s[im][j][1] = -1e30f;
                        if (col     > row_lo + 8) s[im][j][2] = -1e30f;
                        if (col + 1 > row_lo + 8) s[im][j][3] = -1e30f;
                    }
                    tml = fmaxf(tml, fmaxf(s[im][j][0], s[im][j][1]));
                    tmh = fmaxf(tmh, fmaxf(s[im][j][2], s[im][j][3]));
                }
                tml = fmaxf(tml, __shfl_xor_sync(0xffffffffu, tml, 1));
                tml = fmaxf(tml, __shfl_xor_sync(0xffffffffu, tml, 2));
                tmh = fmaxf(tmh, __shfl_xor_sync(0xffffffffu, tmh, 1));
                tmh = fmaxf(tmh, __shfl_xor_sync(0xffffffffu, tmh, 2));

                float mnl = fmaxf(mm[im][0], tml);
                float mnh = fmaxf(mm[im][1], tmh);
                float all = __expf(mm[im][0] - mnl);
                float alh = __expf(mm[im][1] - mnh);
                mm[im][0] = mnl; mm[im][1] = mnh;
                #pragma unroll
                for (int n = 0; n < 8; n++) {
                    o[im][n][0] *= all; o[im][n][1] *= all;
                    o[im][n][2] *= alh; o[im][n][3] *= alh;
                }

                float rsl = 0.0f, rsh = 0.0f;
                const int rl = w * 32 + im * 16 + qrl;
                #pragma unroll
                for (int j = 0; j < 8; j++) {
                    float p0 = __expf(s[im][j][0] - mnl);
                    float p1 = __expf(s[im][j][1] - mnl);
                    float p2 = __expf(s[im][j][2] - mnh);
                    float p3 = __expf(s[im][j][3] - mnh);
                    rsl += p0 + p1;
                    rsh += p2 + p3;
                    *(float2*)&Psm[rl * PSTR + j * 8 + 2 * quad] =
                        make_float2(tf32r(p0), tf32r(p1));
                    *(float2*)&Psm[(rl + 8) * PSTR + j * 8 + 2 * quad] =
                        make_float2(tf32r(p2), tf32r(p3));
                }
                rsl += __shfl_xor_sync(0xffffffffu, rsl, 1);
                rsl += __shfl_xor_sync(0xffffffffu, rsl, 2);
                rsh += __shfl_xor_sync(0xffffffffu, rsh, 1);
                rsh += __shfl_xor_sync(0xffffffffu, rsh, 2);
                ll[im][0] = ll[im][0] * all + rsl;
                ll[im][1] = ll[im][1] * alh + rsh;
            }
            __syncwarp();

            // ---- O += P V ----
            #pragma unroll
            for (int kc = 0; kc < 8; kc++) {
                int kk = kc * 8 + quad;
                unsigned ap[2][4];
                #pragma unroll
                for (int im = 0; im < 2; im++) {
                    int rl = w * 32 + im * 16 + qrl;
                    ap[im][0] = __float_as_uint(Psm[rl * PSTR + kk]);
                    ap[im][1] = __float_as_uint(Psm[(rl + 8) * PSTR + kk]);
                    ap[im][2] = __float_as_uint(Psm[rl * PSTR + kk + 4]);
                    ap[im][3] = __float_as_uint(Psm[(rl + 8) * PSTR + kk + 4]);
                }
                int row0 = kc * 8 + quad;
                int row1 = row0 + 4;
                const float* vp0 = Vs + row0 * 64;
                const float* vp1 = Vs + row1 * 64;
                #pragma unroll
                for (int n = 0; n < 8; n++) {
                    int dd = n * 8 + qrl;
                    unsigned b0 = __float_as_uint(
                        vp0[(((dd >> 2) ^ (row0 & 7)) << 2) + (dd & 3)]);
                    unsigned b1 = __float_as_uint(
                        vp1[(((dd >> 2) ^ (row1 & 7)) << 2) + (dd & 3)]);
                    mma_tf32(o[0][n], ap[0], b0, b1);
                    mma_tf32(o[1][n], ap[1], b0, b1);
                }
            }
        }
        __syncthreads();
    }

    // ---- epilogue: normalize + round (feeds tf32 proj GEMM) ----
    #pragma unroll
    for (int im = 0; im < 2; im++) {
        float invl = 1.0f / ll[im][0];
        float invh = 1.0f / ll[im][1];
        int rl = q0 + w * 32 + im * 16 + qrl;
        #pragma unroll
        for (int n = 0; n < 8; n++) {
            int col = h * HDIM + n * 8 + 2 * quad;
            *(float2*)&g_att[(size_t)rl * CC + col] =
                make_float2(tf32r(o[im][n][0] * invl), tf32r(o[im][n][1] * invl));
            *(float2*)&g_att[(size_t)(rl + 8) * CC + col] =
                make_float2(tf32r(o[im][n][2] * invh), tf32r(o[im][n][3] * invh));
        }
    }
}

// ================================ launch ===================================
extern "C" void kernel_launch(void* const* d_in, const int* in_sizes, int n_in,
                              void* d_out, int out_size)
{
    const float* x      = (const float*)d_in[0];
    const float* W_attn = (const float*)d_in[1];
    const float* b_attn = (const float*)d_in[2];
    const float* W_proj = (const float*)d_in[3];
    const float* b_proj = (const float*)d_in[4];
    float*       out    = (float*)d_out;

    void *qkv_p, *att_p, *xr_p, *wat_p, *wpt_p;
    cudaGetSymbolAddress(&qkv_p, g_qkv);
    cudaGetSymbolAddress(&att_p, g_att);
    cudaGetSymbolAddress(&xr_p,  g_xr);
    cudaGetSymbolAddress(&wat_p, g_wat);
    cudaGetSymbolAddress(&wpt_p, g_wpt);
    float* qkv = (float*)qkv_p;
    float* att = (float*)att_p;
    float* xr  = (float*)xr_p;
    float* wat = (float*)wat_p;
    float* wpt = (float*)wpt_p;

    cudaFuncSetAttribute(gemm_tc,
                         cudaFuncAttributeMaxDynamicSharedMemorySize, GEMM_SMEM);
    cudaFuncSetAttribute(flash_attn_tc,
                         cudaFuncAttributeMaxDynamicSharedMemorySize, ATT_SMEM);

    // 0) pre-pass
    {
        int n4 = TT * CC / 4;
        round_copy<<<(n4 + 255) / 256, 256>>>(x, xr, n4);
        transpose_round<<<dim3(3 * CC / 32, CC / 32), dim3(32, 8)>>>(W_attn, wat, CC, 3 * CC);
        transpose_round<<<dim3(CC / 32, CC / 32), dim3(32, 8)>>>(W_proj, wpt, CC, CC);
    }
    // 1) QKV projection (output rounded for attention operands)
    {
        dim3 grid(3 * CC / 128, TT / 128);
        gemm_tc<<<grid, 256, GEMM_SMEM>>>(xr, wat, b_attn, qkv, TT, 3 * CC, CC, 1);
    }
    // 2) Causal flash attention
    {
        dim3 grid(TT / 256, NHEAD);
        flash_attn_tc<<<grid, 256, ATT_SMEM>>>();
    }
    // 3) Output projection
    {
        dim3 grid(CC / 128, TT / 128);
        gemm_tc<<<grid, 256, GEMM_SMEM>>>(att, wpt, b_proj, out, TT, CC, CC, 0);
    }
}

// round 10
// speedup vs baseline: 1.5799x; 1.1351x over previous
#include <cuda_runtime.h>
#include <cuda_bf16.h>
#include <cstdint>
#include <math.h>

// ---------------------------------------------------------------------------
// GPT2 attention block — tf32 mma.sync.
//   prepass: round x, round+transpose weights
//   x @ W_attn + b_attn -> qkv (rounded)  [gemm_tc: 2-stage cp.async+ldmatrix]
//   flash attention BQ=128 (4 warps), BKV=64, Q in regs, split-P -> att
//   att @ W_proj + b_proj -> out          [gemm_tc]
// ---------------------------------------------------------------------------

#define TT      4096
#define CC      1024
#define NHEAD   16
#define HDIM    64
#define SCALE   0.125f

__device__ float g_qkv[TT * 3 * CC];
__device__ float g_att[TT * CC];
__device__ float g_xr [TT * CC];
__device__ float g_wat[3 * CC * CC];
__device__ float g_wpt[CC * CC];

// ============================ helpers ======================================
__device__ __forceinline__ uint32_t smem_u32(const void* p) {
    uint32_t a;
    asm("{ .reg .u64 t; cvta.to.shared.u64 t, %1; cvt.u32.u64 %0, t; }"
        : "=r"(a) : "l"(p));
    return a;
}
__device__ __forceinline__ unsigned cvt_tf32(float x) {
    unsigned u;
    asm("cvt.rna.tf32.f32 %0, %1;" : "=r"(u) : "f"(x));
    return u;
}
__device__ __forceinline__ float tf32r(float x) {
    return __uint_as_float(cvt_tf32(x));
}
__device__ __forceinline__ void mma_tf32(float* d, const unsigned* a,
                                         unsigned b0, unsigned b1) {
    asm volatile(
        "mma.sync.aligned.m16n8k8.row.col.f32.tf32.tf32.f32 "
        "{%0,%1,%2,%3}, {%4,%5,%6,%7}, {%8,%9}, {%0,%1,%2,%3};"
        : "+f"(d[0]), "+f"(d[1]), "+f"(d[2]), "+f"(d[3])
        : "r"(a[0]), "r"(a[1]), "r"(a[2]), "r"(a[3]), "r"(b0), "r"(b1));
}
__device__ __forceinline__ void ldsm4(unsigned* r, uint32_t addr) {
    asm volatile("ldmatrix.sync.aligned.m8n8.x4.shared.b16 {%0,%1,%2,%3}, [%4];"
                 : "=r"(r[0]), "=r"(r[1]), "=r"(r[2]), "=r"(r[3]) : "r"(addr));
}
__device__ __forceinline__ void cpa16(uint32_t dst, const float* src) {
    asm volatile("cp.async.cg.shared.global [%0], [%1], 16;" :: "r"(dst), "l"(src));
}
#define CP_COMMIT() asm volatile("cp.async.commit_group;" ::: "memory")
#define CP_WAIT1()  asm volatile("cp.async.wait_group 1;" ::: "memory")

// ============================ pre-pass kernels =============================
__global__ void round_copy(const float* __restrict__ in, float* __restrict__ out, int n4) {
    int i = blockIdx.x * blockDim.x + threadIdx.x;
    if (i < n4) {
        float4 v = ((const float4*)in)[i];
        v.x = tf32r(v.x); v.y = tf32r(v.y); v.z = tf32r(v.z); v.w = tf32r(v.w);
        ((float4*)out)[i] = v;
    }
}
__global__ void transpose_round(const float* __restrict__ W, float* __restrict__ Wt,
                                int K, int N) {
    __shared__ float t[32][33];
    int n0 = blockIdx.x * 32, k0 = blockIdx.y * 32;
    int tx = threadIdx.x, ty = threadIdx.y;
    #pragma unroll
    for (int j = 0; j < 32; j += 8)
        t[ty + j][tx] = W[(size_t)(k0 + ty + j) * N + n0 + tx];
    __syncthreads();
    #pragma unroll
    for (int j = 0; j < 32; j += 8)
        Wt[(size_t)(n0 + ty + j) * K + k0 + tx] = tf32r(t[tx][ty + j]);
}

// ============================ GEMM (round-8 2-stage) =======================
#define GEMM_SMEM 65536

__global__ __launch_bounds__(256, 2)
void gemm_tc(const float* __restrict__ A, const float* __restrict__ Bt,
             const float* __restrict__ bias, float* __restrict__ C,
             int M, int N, int K, int round_out)
{
    extern __shared__ char dsm[];
    const uint32_t sb = smem_u32(dsm);

    const int tid  = threadIdx.x;
    const int lane = tid & 31;
    const int qrl  = lane >> 2;
    const int quad = lane & 3;
    const int w    = tid >> 5;
    const int wm   = w >> 2;
    const int wn   = w & 3;
    const int bm   = blockIdx.y * 128;
    const int bn   = blockIdx.x * 128;

    float d[4][4][4];
    #pragma unroll
    for (int im = 0; im < 4; im++)
        #pragma unroll
        for (int jn = 0; jn < 4; jn++)
            #pragma unroll
            for (int r = 0; r < 4; r++) d[im][jn][r] = 0.0f;

    const int r  = tid >> 1;
    const int c0 = (tid & 1) * 4;
    const float* gA = A  + (size_t)(bm + r) * K;
    const float* gB = Bt + (size_t)(bn + r) * K;
    const uint32_t rowoff = (uint32_t)r * 128u;
    const int rx = r & 7;

    const int NST = K / 32;

    #pragma unroll
    for (int i = 0; i < 4; i++) {
        int c = c0 + i;
        uint32_t doff = rowoff + (uint32_t)((c ^ rx) << 4);
        cpa16(sb + doff,          gA + c * 4);
        cpa16(sb + 16384 + doff,  gB + c * 4);
    }
    CP_COMMIT();

    const int mtx = lane >> 3;
    const int rr  = lane & 7;

    for (int s = 0; s < NST; s++) {
        if (s + 1 < NST) {
            const uint32_t slot = (uint32_t)((s + 1) & 1) * 32768u;
            const int k0 = (s + 1) * 32;
            #pragma unroll
            for (int i = 0; i < 4; i++) {
                int c = c0 + i;
                uint32_t doff = slot + rowoff + (uint32_t)((c ^ rx) << 4);
                cpa16(sb + doff,         gA + k0 + c * 4);
                cpa16(sb + 16384 + doff, gB + k0 + c * 4);
            }
        }
        CP_COMMIT();
        CP_WAIT1();
        __syncthreads();

        const uint32_t Ab = sb + (uint32_t)(s & 1) * 32768u;
        const uint32_t Bb = Ab + 16384u;

        #pragma unroll
        for (int ks = 0; ks < 4; ks++) {
            unsigned a[4][4];
            #pragma unroll
            for (int im = 0; im < 4; im++) {
                int m_row = wm * 64 + im * 16 + rr + ((mtx & 1) << 3);
                int kch   = ks * 2 + (mtx >> 1);
                uint32_t addr = Ab + (uint32_t)m_row * 128u
                              + (uint32_t)((kch ^ (m_row & 7)) << 4);
                ldsm4(a[im], addr);
            }
            unsigned b[2][4];
            #pragma unroll
            for (int j2 = 0; j2 < 2; j2++) {
                int n_row = wn * 32 + j2 * 16 + rr + ((mtx >> 1) << 3);
                int kch   = ks * 2 + (mtx & 1);
                uint32_t addr = Bb + (uint32_t)n_row * 128u
                              + (uint32_t)((kch ^ (n_row & 7)) << 4);
                ldsm4(b[j2], addr);
            }
            #pragma unroll
            for (int im = 0; im < 4; im++)
                #pragma unroll
                for (int jn = 0; jn < 4; jn++)
                    mma_tf32(d[im][jn], a[im],
                             b[jn >> 1][(jn & 1) * 2],
                             b[jn >> 1][(jn & 1) * 2 + 1]);
        }
        __syncthreads();
    }

    #pragma unroll
    for (int im = 0; im < 4; im++) {
        int r_lo = bm + wm * 64 + im * 16 + qrl;
        #pragma unroll
        for (int jn = 0; jn < 4; jn++) {
            int col = bn + wn * 32 + jn * 8 + 2 * quad;
            float b0 = bias[col], b1 = bias[col + 1];
            float2 v0, v1;
            if (round_out) {
                v0 = make_float2(tf32r(d[im][jn][0] + b0), tf32r(d[im][jn][1] + b1));
                v1 = make_float2(tf32r(d[im][jn][2] + b0), tf32r(d[im][jn][3] + b1));
            } else {
                v0 = make_float2(d[im][jn][0] + b0, d[im][jn][1] + b1);
                v1 = make_float2(d[im][jn][2] + b0, d[im][jn][3] + b1);
            }
            *(float2*)&C[(size_t)r_lo * N + col]       = v0;
            *(float2*)&C[(size_t)(r_lo + 8) * N + col] = v1;
        }
    }
}

// ============================ flash attention ==============================
// BQ=128 q rows/block, 4 warps x 32 q rows (2 m-tiles), BKV=64 keys/tile.
// Q in registers. K/V cp.async double-buffered swizzled tiles.
// P through smem in two 32-key halves (PSTR2=36) -> 84KB smem, 2 blocks/SM.
#define PSTR2 36
#define ATT_SMEM (65536 + 128 * PSTR2 * 4)

__device__ __forceinline__ void att_stage(uint32_t sb, int tid, int h, int kt) {
    const uint32_t kslot = sb + (uint32_t)(kt & 1) * 16384u;
    const uint32_t vslot = sb + 32768u + (uint32_t)(kt & 1) * 16384u;
    const int k0 = kt * 64;
    #pragma unroll
    for (int i = 0; i < 8; i++) {
        int idx = tid + i * 128;
        int r = idx >> 4, c = idx & 15;
        const float* src = &g_qkv[(size_t)(k0 + r) * (3 * CC) + CC + h * HDIM + c * 4];
        uint32_t doff = (uint32_t)r * 256u + (uint32_t)((c ^ (r & 7)) << 4);
        cpa16(kslot + doff, src);
        cpa16(vslot + doff, src + CC);
    }
}

__global__ __launch_bounds__(128)
void flash_attn_tc()
{
    extern __shared__ char asmem[];
    const uint32_t sb = smem_u32(asmem);
    float* Psm = (float*)(asmem + 65536);

    const int h    = blockIdx.y;
    const int qt   = 31 - (int)blockIdx.x;   // heavy first
    const int q0   = qt * 128;
    const int tid  = threadIdx.x;
    const int lane = tid & 31;
    const int w    = tid >> 5;               // 0..3
    const int qrl  = lane >> 2;
    const int quad = lane & 3;

    // ---- Q fragments in registers (qkv pre-rounded to tf32 values) ----
    unsigned qa[2][8][4];
    #pragma unroll
    for (int im = 0; im < 2; im++) {
        int row = q0 + w * 32 + im * 16 + qrl;
        const float* p0 = &g_qkv[(size_t)row * (3 * CC) + h * HDIM + quad];
        const float* p1 = p0 + (size_t)8 * (3 * CC);
        #pragma unroll
        for (int ks = 0; ks < 8; ks++) {
            qa[im][ks][0] = __float_as_uint(p0[ks * 8]);
            qa[im][ks][1] = __float_as_uint(p1[ks * 8]);
            qa[im][ks][2] = __float_as_uint(p0[ks * 8 + 4]);
            qa[im][ks][3] = __float_as_uint(p1[ks * 8 + 4]);
        }
    }

    float o[2][8][4];
    #pragma unroll
    for (int im = 0; im < 2; im++)
        #pragma unroll
        for (int n = 0; n < 8; n++)
            #pragma unroll
            for (int r = 0; r < 4; r++) o[im][n][r] = 0.0f;
    float mm[2][2] = {{-1e30f, -1e30f}, {-1e30f, -1e30f}};
    float ll[2][2] = {{0.0f, 0.0f}, {0.0f, 0.0f}};

    const int n_tiles = 2 * (qt + 1);

    att_stage(sb, tid, h, 0);
    CP_COMMIT();

    for (int kt = 0; kt < n_tiles; kt++) {
        if (kt + 1 < n_tiles) att_stage(sb, tid, h, kt + 1);
        CP_COMMIT();
        CP_WAIT1();
        __syncthreads();

        const float* Ks = (const float*)(asmem + (kt & 1) * 16384);
        const float* Vs = (const float*)(asmem + 32768 + (kt & 1) * 16384);
        const int k0 = kt * 64;
        const bool active = (k0 < q0 + w * 32 + 32);

        if (active) {
            // ---- S = Q K^T ----
            float s[2][8][4];
            #pragma unroll
            for (int im = 0; im < 2; im++)
                #pragma unroll
                for (int j = 0; j < 8; j++)
                    #pragma unroll
                    for (int r = 0; r < 4; r++) s[im][j][r] = 0.0f;

            #pragma unroll
            for (int ks = 0; ks < 8; ks++) {
                #pragma unroll
                for (int j = 0; j < 8; j++) {
                    int row = j * 8 + qrl;
                    const float* rp = Ks + row * 64;
                    unsigned b0 = __float_as_uint(rp[(((2 * ks)     ^ (row & 7)) << 2) + quad]);
                    unsigned b1 = __float_as_uint(rp[(((2 * ks + 1) ^ (row & 7)) << 2) + quad]);
                    mma_tf32(s[0][j], qa[0][ks], b0, b1);
                    mma_tf32(s[1][j], qa[1][ks], b0, b1);
                }
            }

            // ---- scale + mask + full-tile row max + rescale O ----
            float mn[2][2], al[2][2];
            #pragma unroll
            for (int im = 0; im < 2; im++) {
                const int base   = q0 + w * 32 + im * 16;
                const int row_lo = base + qrl;
                const bool domask = (k0 + 63 > base);
                float tml = -1e30f, tmh = -1e30f;
                #pragma unroll
                for (int j = 0; j < 8; j++) {
                    #pragma unroll
                    for (int r2 = 0; r2 < 4; r2++) s[im][j][r2] *= SCALE;
                    if (domask) {
                        int col = k0 + j * 8 + 2 * quad;
                        if (col     > row_lo)     s[im][j][0] = -1e30f;
                        if (col + 1 > row_lo)     s[im][j][1] = -1e30f;
                        if (col     > row_lo + 8) s[im][j][2] = -1e30f;
                        if (col + 1 > row_lo + 8) s[im][j][3] = -1e30f;
                    }
                    tml = fmaxf(tml, fmaxf(s[im][j][0], s[im][j][1]));
                    tmh = fmaxf(tmh, fmaxf(s[im][j][2], s[im][j][3]));
                }
                tml = fmaxf(tml, __shfl_xor_sync(0xffffffffu, tml, 1));
                tml = fmaxf(tml, __shfl_xor_sync(0xffffffffu, tml, 2));
                tmh = fmaxf(tmh, __shfl_xor_sync(0xffffffffu, tmh, 1));
                tmh = fmaxf(tmh, __shfl_xor_sync(0xffffffffu, tmh, 2));

                mn[im][0] = fmaxf(mm[im][0], tml);
                mn[im][1] = fmaxf(mm[im][1], tmh);
                al[im][0] = __expf(mm[im][0] - mn[im][0]);
                al[im][1] = __expf(mm[im][1] - mn[im][1]);
                mm[im][0] = mn[im][0]; mm[im][1] = mn[im][1];
                #pragma unroll
                for (int n = 0; n < 8; n++) {
                    o[im][n][0] *= al[im][0]; o[im][n][1] *= al[im][0];
                    o[im][n][2] *= al[im][1]; o[im][n][3] *= al[im][1];
                }
            }

            // ---- two 32-key halves: exp + store P, then PV ----
            float rs[2][2] = {{0.0f, 0.0f}, {0.0f, 0.0f}};
            #pragma unroll
            for (int hf = 0; hf < 2; hf++) {
                #pragma unroll
                for (int im = 0; im < 2; im++) {
                    const int rl = w * 32 + im * 16 + qrl;
                    #pragma unroll
                    for (int jj = 0; jj < 4; jj++) {
                        int j = hf * 4 + jj;
                        float p0 = __expf(s[im][j][0] - mn[im][0]);
                        float p1 = __expf(s[im][j][1] - mn[im][0]);
                        float p2 = __expf(s[im][j][2] - mn[im][1]);
                        float p3 = __expf(s[im][j][3] - mn[im][1]);
                        rs[im][0] += p0 + p1;
                        rs[im][1] += p2 + p3;
                        *(float2*)&Psm[rl * PSTR2 + jj * 8 + 2 * quad] =
                            make_float2(tf32r(p0), tf32r(p1));
                        *(float2*)&Psm[(rl + 8) * PSTR2 + jj * 8 + 2 * quad] =
                            make_float2(tf32r(p2), tf32r(p3));
                    }
                }
                __syncwarp();

                #pragma unroll
                for (int kc = 0; kc < 4; kc++) {
                    int kk = kc * 8 + quad;
                    unsigned ap[2][4];
                    #pragma unroll
                    for (int im = 0; im < 2; im++) {
                        int rl = w * 32 + im * 16 + qrl;
                        ap[im][0] = __float_as_uint(Psm[rl * PSTR2 + kk]);
                        ap[im][1] = __float_as_uint(Psm[(rl + 8) * PSTR2 + kk]);
                        ap[im][2] = __float_as_uint(Psm[rl * PSTR2 + kk + 4]);
                        ap[im][3] = __float_as_uint(Psm[(rl + 8) * PSTR2 + kk + 4]);
                    }
                    int row0 = (hf * 4 + kc) * 8 + quad;
                    int row1 = row0 + 4;
                    const float* vp0 = Vs + row0 * 64;
                    const float* vp1 = Vs + row1 * 64;
                    #pragma unroll
                    for (int n = 0; n < 8; n++) {
                        int dd = n * 8 + qrl;
                        unsigned b0 = __float_as_uint(
                            vp0[(((dd >> 2) ^ (row0 & 7)) << 2) + (dd & 3)]);
                        unsigned b1 = __float_as_uint(
                            vp1[(((dd >> 2) ^ (row1 & 7)) << 2) + (dd & 3)]);
                        mma_tf32(o[0][n], ap[0], b0, b1);
                        mma_tf32(o[1][n], ap[1], b0, b1);
                    }
                }
                __syncwarp();
            }

            // ---- l update ----
            #pragma unroll
            for (int im = 0; im < 2; im++) {
                float rsl = rs[im][0], rsh = rs[im][1];
                rsl += __shfl_xor_sync(0xffffffffu, rsl, 1);
                rsl += __shfl_xor_sync(0xffffffffu, rsl, 2);
                rsh += __shfl_xor_sync(0xffffffffu, rsh, 1);
                rsh += __shfl_xor_sync(0xffffffffu, rsh, 2);
                ll[im][0] = ll[im][0] * al[im][0] + rsl;
                ll[im][1] = ll[im][1] * al[im][1] + rsh;
            }
        }
        __syncthreads();
    }

    // ---- epilogue: normalize + round (feeds tf32 proj GEMM) ----
    #pragma unroll
    for (int im = 0; im < 2; im++) {
        float invl = 1.0f / ll[im][0];
        float invh = 1.0f / ll[im][1];
        int rl = q0 + w * 32 + im * 16 + qrl;
        #pragma unroll
        for (int n = 0; n < 8; n++) {
            int col = h * HDIM + n * 8 + 2 * quad;
            *(float2*)&g_att[(size_t)rl * CC + col] =
                make_float2(tf32r(o[im][n][0] * invl), tf32r(o[im][n][1] * invl));
            *(float2*)&g_att[(size_t)(rl + 8) * CC + col] =
                make_float2(tf32r(o[im][n][2] * invh), tf32r(o[im][n][3] * invh));
        }
    }
}

// ================================ launch ===================================
extern "C" void kernel_launch(void* const* d_in, const int* in_sizes, int n_in,
                              void* d_out, int out_size)
{
    const float* x      = (const float*)d_in[0];
    const float* W_attn = (const float*)d_in[1];
    const float* b_attn = (const float*)d_in[2];
    const float* W_proj = (const float*)d_in[3];
    const float* b_proj = (const float*)d_in[4];
    float*       out    = (float*)d_out;

    void *qkv_p, *att_p, *xr_p, *wat_p, *wpt_p;
    cudaGetSymbolAddress(&qkv_p, g_qkv);
    cudaGetSymbolAddress(&att_p, g_att);
    cudaGetSymbolAddress(&xr_p,  g_xr);
    cudaGetSymbolAddress(&wat_p, g_wat);
    cudaGetSymbolAddress(&wpt_p, g_wpt);
    float* qkv = (float*)qkv_p;
    float* att = (float*)att_p;
    float* xr  = (float*)xr_p;
    float* wat = (float*)wat_p;
    float* wpt = (float*)wpt_p;

    cudaFuncSetAttribute(gemm_tc,
                         cudaFuncAttributeMaxDynamicSharedMemorySize, GEMM_SMEM);
    cudaFuncSetAttribute(flash_attn_tc,
                         cudaFuncAttributeMaxDynamicSharedMemorySize, ATT_SMEM);

    // 0) pre-pass
    {
        int n4 = TT * CC / 4;
        round_copy<<<(n4 + 255) / 256, 256>>>(x, xr, n4);
        transpose_round<<<dim3(3 * CC / 32, CC / 32), dim3(32, 8)>>>(W_attn, wat, CC, 3 * CC);
        transpose_round<<<dim3(CC / 32, CC / 32), dim3(32, 8)>>>(W_proj, wpt, CC, CC);
    }
    // 1) QKV projection (output rounded for attention operands)
    {
        dim3 grid(3 * CC / 128, TT / 128);
        gemm_tc<<<grid, 256, GEMM_SMEM>>>(xr, wat, b_attn, qkv, TT, 3 * CC, CC, 1);
    }
    // 2) Causal flash attention
    {
        dim3 grid(TT / 128, NHEAD);
        flash_attn_tc<<<grid, 128, ATT_SMEM>>>();
    }
    // 3) Output projection
    {
        dim3 grid(CC / 128, TT / 128);
        gemm_tc<<<grid, 256, GEMM_SMEM>>>(att, wpt, b_proj, out, TT, CC, CC, 0);
    }
}